// round 1
// baseline (speedup 1.0000x reference)
#include <cuda_runtime.h>

#define NUSER 50000
#define NITEM 100000
#define NN    150000
#define DD    64
#define EE    2400000

// scratch: static device globals (no runtime allocation allowed)
__device__ float g_ego[NN * DD];   // 38.4 MB
__device__ float g_side[NN * DD];  // 38.4 MB

// ---------------------------------------------------------------------------
// init: ego = concat(user_emb, item_emb); side = 0; out[:, 0:64] = ego
// float4-vectorized over NN*16 float4s.
// ---------------------------------------------------------------------------
__global__ void init_kernel(const float* __restrict__ ue,
                            const float* __restrict__ ie,
                            float* __restrict__ out) {
    int i4 = blockIdx.x * blockDim.x + threadIdx.x;  // float4 index
    if (i4 >= NN * 16) return;
    int row = i4 >> 4;
    int q   = i4 & 15;
    float4 v;
    if (row < NUSER) v = reinterpret_cast<const float4*>(ue)[i4];
    else             v = reinterpret_cast<const float4*>(ie)[i4 - NUSER * 16];
    reinterpret_cast<float4*>(g_ego)[i4]  = v;
    reinterpret_cast<float4*>(g_side)[i4] = make_float4(0.f, 0.f, 0.f, 0.f);
    // out row stride = 256 floats = 64 float4; first 16 float4s are block 0
    reinterpret_cast<float4*>(out)[row * 64 + q] = v;
}

// ---------------------------------------------------------------------------
// SpMM: side[r] += vals[e] * ego[c] for each COO edge.
// Thread = (edge, quarter): 16 threads/edge, each handles one float4.
// ego gather and side RED are contiguous 256B per edge -> coalesced.
// float4 atomicAdd (sm_90+) cuts RED count 4x vs scalar.
// ---------------------------------------------------------------------------
__global__ void spmm_kernel(const float* __restrict__ vals,
                            const int*   __restrict__ rows,
                            const int*   __restrict__ cols) {
    int t = blockIdx.x * blockDim.x + threadIdx.x;  // EE*16 = 38.4M < 2^31
    if (t >= EE * 16) return;
    int e = t >> 4;
    int q = t & 15;
    int c   = __ldg(cols + e);
    int r   = __ldg(rows + e);
    float v = __ldg(vals + e);
    float4 x = *reinterpret_cast<const float4*>(g_ego + (size_t)c * DD + q * 4);
    x.x *= v; x.y *= v; x.z *= v; x.w *= v;
#if __CUDA_ARCH__ >= 900
    atomicAdd(reinterpret_cast<float4*>(g_side + (size_t)r * DD + q * 4), x);
#else
    float* p = g_side + (size_t)r * DD + q * 4;
    atomicAdd(p + 0, x.x); atomicAdd(p + 1, x.y);
    atomicAdd(p + 2, x.z); atomicAdd(p + 3, x.w);
#endif
}

// ---------------------------------------------------------------------------
// Fused dense layer:
//   sum = leaky(side @ Wg + bg); bi = leaky((ego*side) @ Wb + bb)
//   ego = sum + bi;  out[:, koff:koff+64] = l2norm(ego);  side = 0 (for next)
// Block = 256 threads = 4 rows x 64 cols. Weights staged in smem (32 KB).
// Thread j owns output column j of its row: W[i*64+j] smem reads are
// conflict-free (consecutive lanes), side[i]/es[i] are broadcasts.
// ---------------------------------------------------------------------------
__global__ __launch_bounds__(256) void layer_kernel(
    const float* __restrict__ Wg, const float* __restrict__ bg,
    const float* __restrict__ Wb, const float* __restrict__ bb,
    float* __restrict__ out, int koff) {
    __shared__ float sWg[64 * 64];
    __shared__ float sWb[64 * 64];
    __shared__ float sS[4][64];
    __shared__ float sES[4][64];
    __shared__ float sRed[8];

    int tid = threadIdx.x;
    // stage weights: 4096 floats each, 16 per thread
#pragma unroll
    for (int i = 0; i < 16; i++) {
        sWg[tid + i * 256] = Wg[tid + i * 256];
        sWb[tid + i * 256] = Wb[tid + i * 256];
    }

    int grp  = tid >> 6;
    int lane = tid & 63;
    int row  = blockIdx.x * 4 + grp;

    float sv = g_side[row * 64 + lane];
    float ev = g_ego[row * 64 + lane];
    sS[grp][lane]  = sv;
    sES[grp][lane] = ev * sv;
    g_side[row * 64 + lane] = 0.f;  // clear for next layer's SpMM
    __syncthreads();

    float accg = __ldg(bg + lane);
    float accb = __ldg(bb + lane);
#pragma unroll
    for (int i = 0; i < 64; i++) {
        accg = fmaf(sS[grp][i],  sWg[i * 64 + lane], accg);
        accb = fmaf(sES[grp][i], sWb[i * 64 + lane], accb);
    }
    // LeakyReLU(0.2)
    accg = (accg > 0.f) ? accg : 0.2f * accg;
    accb = (accb > 0.f) ? accb : 0.2f * accb;
    float ne = accg + accb;
    g_ego[row * 64 + lane] = ne;  // ego stays UNnormalized (reference semantics)

    // l2 norm across the 64 values of this row (2 warps)
    float sq = ne * ne;
#pragma unroll
    for (int off = 16; off > 0; off >>= 1)
        sq += __shfl_xor_sync(0xffffffffu, sq, off);
    int wid = tid >> 5;
    if ((tid & 31) == 0) sRed[wid] = sq;
    __syncthreads();
    float nrm = sqrtf(sRed[grp * 2] + sRed[grp * 2 + 1]);
    nrm = fmaxf(nrm, 1e-12f);
    out[row * 256 + koff + lane] = ne / nrm;
}

// ---------------------------------------------------------------------------
extern "C" void kernel_launch(void* const* d_in, const int* in_sizes, int n_in,
                              void* d_out, int out_size) {
    const float* ue = (const float*)d_in[0];
    const float* ie = (const float*)d_in[1];
    const float* Wg[3] = {(const float*)d_in[2],  (const float*)d_in[6],  (const float*)d_in[10]};
    const float* bg[3] = {(const float*)d_in[3],  (const float*)d_in[7],  (const float*)d_in[11]};
    const float* Wb[3] = {(const float*)d_in[4],  (const float*)d_in[8],  (const float*)d_in[12]};
    const float* bb[3] = {(const float*)d_in[5],  (const float*)d_in[9],  (const float*)d_in[13]};
    const float* vals = (const float*)d_in[14];
    const int*   rows = (const int*)d_in[15];
    const int*   cols = (const int*)d_in[16];
    float* out = (float*)d_out;

    init_kernel<<<(NN * 16 + 255) / 256, 256>>>(ue, ie, out);
    for (int k = 0; k < 3; k++) {
        spmm_kernel<<<(EE * 16 + 255) / 256, 256>>>(vals, rows, cols);
        layer_kernel<<<NN / 4, 256>>>(Wg[k], bg[k], Wb[k], bb[k], out, (k + 1) * 64);
    }
}

// round 2
// speedup vs baseline: 1.2448x; 1.2448x over previous
#include <cuda_runtime.h>

#define NUSER 50000
#define NITEM 100000
#define NN    150000
#define DD    64
#define EE    2400000

// scratch: static device globals (no runtime allocation allowed)
__device__ float g_ego[NN * DD];   // 38.4 MB
__device__ float g_side[NN * DD];  // 38.4 MB

// ---------------------------------------------------------------------------
// init: ego = concat(user_emb, item_emb); side = 0; out[:, 0:64] = ego (raw)
// ---------------------------------------------------------------------------
__global__ void init_kernel(const float* __restrict__ ue,
                            const float* __restrict__ ie,
                            float* __restrict__ out) {
    int i4 = blockIdx.x * blockDim.x + threadIdx.x;  // float4 index
    if (i4 >= NN * 16) return;
    int row = i4 >> 4;
    int q   = i4 & 15;
    float4 v;
    if (row < NUSER) v = reinterpret_cast<const float4*>(ue)[i4];
    else             v = reinterpret_cast<const float4*>(ie)[i4 - NUSER * 16];
    reinterpret_cast<float4*>(g_ego)[i4]  = v;
    reinterpret_cast<float4*>(g_side)[i4] = make_float4(0.f, 0.f, 0.f, 0.f);
    reinterpret_cast<float4*>(out)[row * 64 + q] = v;
}

// ---------------------------------------------------------------------------
// SpMM: side[r] += vals[e] * ego[c].  4 threads/edge, each owns 4 float4s
// (MLP=4: all 4 gathers issued before the 4 REDs). Per load j, the 4 lanes of
// an edge cover contiguous 64B -> coalesced.
// ---------------------------------------------------------------------------
__global__ void spmm_kernel(const float* __restrict__ vals,
                            const int*   __restrict__ rows,
                            const int*   __restrict__ cols) {
    int t = blockIdx.x * blockDim.x + threadIdx.x;  // EE*4 = 9.6M
    if (t >= EE * 4) return;
    int e = t >> 2;
    int q = t & 3;
    int c   = __ldg(cols + e);
    int r   = __ldg(rows + e);
    float v = __ldg(vals + e);
    const float4* src = reinterpret_cast<const float4*>(g_ego + (size_t)c * DD) + q;
    float4*       dst = reinterpret_cast<float4*>(g_side + (size_t)r * DD) + q;

    float4 x[4];
#pragma unroll
    for (int j = 0; j < 4; j++) x[j] = __ldg(src + j * 4);   // independent: MLP=4
#pragma unroll
    for (int j = 0; j < 4; j++) {
        x[j].x *= v; x[j].y *= v; x[j].z *= v; x[j].w *= v;
#if __CUDA_ARCH__ >= 900
        atomicAdd(dst + j * 4, x[j]);
#else
        float* p = reinterpret_cast<float*>(dst + j * 4);
        atomicAdd(p + 0, x[j].x); atomicAdd(p + 1, x[j].y);
        atomicAdd(p + 2, x[j].z); atomicAdd(p + 3, x[j].w);
#endif
    }
}

// ---------------------------------------------------------------------------
// Fused dense layer, register-tiled:
//   Block = 256 threads (16x16), tile = 64 rows x 64 cols, thread = 4x4.
//   sum = leaky(side@Wg+bg); bi = leaky((ego*side)@Wb+bb); ego = sum+bi
//   out[:, koff:+64] = l2norm(ego); side cleared during staging.
// A staged in k-chunks of 16 (smem 41KB total). L2 norm via shfl over the
// 16-lane tx group (row lives entirely within one ty).
// ---------------------------------------------------------------------------
__global__ __launch_bounds__(256) void layer_kernel(
    const float* __restrict__ Wg, const float* __restrict__ bg,
    const float* __restrict__ Wb, const float* __restrict__ bb,
    float* __restrict__ out, int koff) {
    __shared__ float sWg[64 * 64];
    __shared__ float sWb[64 * 64];
    __shared__ float sA [64][17];
    __shared__ float sA2[64][17];

    int tid = threadIdx.x;
#pragma unroll
    for (int i = 0; i < 16; i++) {
        sWg[tid + i * 256] = Wg[tid + i * 256];
        sWb[tid + i * 256] = Wb[tid + i * 256];
    }
    int tx = tid & 15, ty = tid >> 4;
    int c0 = tx * 4,  r0 = ty * 4;
    int rowbase = blockIdx.x * 64;

    float accg[4][4], accb[4][4];
#pragma unroll
    for (int j = 0; j < 4; j++)
#pragma unroll
        for (int i = 0; i < 4; i++) { accg[j][i] = 0.f; accb[j][i] = 0.f; }

    for (int kc = 0; kc < 4; kc++) {
        __syncthreads();
        // stage A chunk [64 rows][16 k] ; also clear side for next SpMM
#pragma unroll
        for (int p = 0; p < 4; p++) {
            int id = tid + p * 256;
            int lr = id >> 4, lc = id & 15;
            int grow = rowbase + lr;
            float sv = 0.f, ev = 0.f;
            if (grow < NN) {
                int gi = grow * 64 + kc * 16 + lc;
                sv = g_side[gi];
                ev = g_ego[gi];
                g_side[gi] = 0.f;
            }
            sA [lr][lc] = sv;
            sA2[lr][lc] = ev * sv;
        }
        __syncthreads();
#pragma unroll
        for (int kk = 0; kk < 16; kk++) {
            int k = kc * 16 + kk;
            float4 wg = *reinterpret_cast<const float4*>(&sWg[k * 64 + c0]);
            float4 wb = *reinterpret_cast<const float4*>(&sWb[k * 64 + c0]);
#pragma unroll
            for (int j = 0; j < 4; j++) {
                float a  = sA [r0 + j][kk];
                float a2 = sA2[r0 + j][kk];
                accg[j][0] = fmaf(a, wg.x, accg[j][0]);
                accg[j][1] = fmaf(a, wg.y, accg[j][1]);
                accg[j][2] = fmaf(a, wg.z, accg[j][2]);
                accg[j][3] = fmaf(a, wg.w, accg[j][3]);
                accb[j][0] = fmaf(a2, wb.x, accb[j][0]);
                accb[j][1] = fmaf(a2, wb.y, accb[j][1]);
                accb[j][2] = fmaf(a2, wb.z, accb[j][2]);
                accb[j][3] = fmaf(a2, wb.w, accb[j][3]);
            }
        }
    }

    float4 bgv = __ldg(reinterpret_cast<const float4*>(bg + c0));
    float4 bbv = __ldg(reinterpret_cast<const float4*>(bb + c0));
    float bga[4] = {bgv.x, bgv.y, bgv.z, bgv.w};
    float bba[4] = {bbv.x, bbv.y, bbv.z, bbv.w};

#pragma unroll
    for (int j = 0; j < 4; j++) {
        float ne[4];
        float s = 0.f;
#pragma unroll
        for (int i = 0; i < 4; i++) {
            float g = accg[j][i] + bga[i];
            float b = accb[j][i] + bba[i];
            g = (g > 0.f) ? g : 0.2f * g;
            b = (b > 0.f) ? b : 0.2f * b;
            ne[i] = g + b;
            s = fmaf(ne[i], ne[i], s);
        }
        // reduce sum of squares across the 16 tx lanes (same row)
#pragma unroll
        for (int m = 8; m > 0; m >>= 1)
            s += __shfl_xor_sync(0xffffffffu, s, m);
        int grow = rowbase + r0 + j;
        if (grow < NN) {
            float inv = 1.f / fmaxf(sqrtf(s), 1e-12f);
            *reinterpret_cast<float4*>(&g_ego[grow * 64 + c0]) =
                make_float4(ne[0], ne[1], ne[2], ne[3]);
            *reinterpret_cast<float4*>(&out[grow * 256 + koff + c0]) =
                make_float4(ne[0] * inv, ne[1] * inv, ne[2] * inv, ne[3] * inv);
        }
    }
}

// ---------------------------------------------------------------------------
extern "C" void kernel_launch(void* const* d_in, const int* in_sizes, int n_in,
                              void* d_out, int out_size) {
    const float* ue = (const float*)d_in[0];
    const float* ie = (const float*)d_in[1];
    const float* Wg[3] = {(const float*)d_in[2],  (const float*)d_in[6],  (const float*)d_in[10]};
    const float* bg[3] = {(const float*)d_in[3],  (const float*)d_in[7],  (const float*)d_in[11]};
    const float* Wb[3] = {(const float*)d_in[4],  (const float*)d_in[8],  (const float*)d_in[12]};
    const float* bb[3] = {(const float*)d_in[5],  (const float*)d_in[9],  (const float*)d_in[13]};
    const float* vals = (const float*)d_in[14];
    const int*   rows = (const int*)d_in[15];
    const int*   cols = (const int*)d_in[16];
    float* out = (float*)d_out;

    init_kernel<<<(NN * 16 + 255) / 256, 256>>>(ue, ie, out);
    for (int k = 0; k < 3; k++) {
        spmm_kernel<<<(EE * 4 + 255) / 256, 256>>>(vals, rows, cols);
        layer_kernel<<<(NN + 63) / 64, 256>>>(Wg[k], bg[k], Wb[k], bb[k], out, (k + 1) * 64);
    }
}

// round 4
// speedup vs baseline: 1.8517x; 1.4875x over previous
#include <cuda_runtime.h>

#define NUSER 50000
#define NITEM 100000
#define NN    150000
#define DD    64
#define EE    2400000

// scratch: static device globals (no runtime allocation allowed)
__device__ float g_ego[NN * DD];   // 38.4 MB
__device__ float g_side[NN * DD];  // 38.4 MB

// tiny shim so ncu (-s 5 -c 1) lands on a layer_kernel launch next capture
__global__ void prof_shim_kernel() {}

// ---------------------------------------------------------------------------
// init: ego = concat(user_emb, item_emb); side = 0; out[:, 0:64] = ego (raw)
// ---------------------------------------------------------------------------
__global__ void init_kernel(const float* __restrict__ ue,
                            const float* __restrict__ ie,
                            float* __restrict__ out) {
    int i4 = blockIdx.x * blockDim.x + threadIdx.x;  // float4 index
    if (i4 >= NN * 16) return;
    int row = i4 >> 4;
    int q   = i4 & 15;
    float4 v;
    if (row < NUSER) v = reinterpret_cast<const float4*>(ue)[i4];
    else             v = reinterpret_cast<const float4*>(ie)[i4 - NUSER * 16];
    reinterpret_cast<float4*>(g_ego)[i4]  = v;
    reinterpret_cast<float4*>(g_side)[i4] = make_float4(0.f, 0.f, 0.f, 0.f);
    reinterpret_cast<float4*>(out)[row * 64 + q] = v;
}

// ---------------------------------------------------------------------------
// SpMM: side[r] += vals[e] * ego[c].  4 threads/edge, each owns 4 float4s
// (MLP=4: all 4 gathers issued before the 4 REDs).
// ---------------------------------------------------------------------------
__global__ void spmm_kernel(const float* __restrict__ vals,
                            const int*   __restrict__ rows,
                            const int*   __restrict__ cols) {
    int t = blockIdx.x * blockDim.x + threadIdx.x;  // EE*4 = 9.6M
    if (t >= EE * 4) return;
    int e = t >> 2;
    int q = t & 3;
    int c   = __ldg(cols + e);
    int r   = __ldg(rows + e);
    float v = __ldg(vals + e);
    const float4* src = reinterpret_cast<const float4*>(g_ego + (size_t)c * DD) + q;
    float4*       dst = reinterpret_cast<float4*>(g_side + (size_t)r * DD) + q;

    float4 x[4];
#pragma unroll
    for (int j = 0; j < 4; j++) x[j] = __ldg(src + j * 4);   // independent: MLP=4
#pragma unroll
    for (int j = 0; j < 4; j++) {
        x[j].x *= v; x[j].y *= v; x[j].z *= v; x[j].w *= v;
#if __CUDA_ARCH__ >= 900
        atomicAdd(dst + j * 4, x[j]);
#else
        float* p = reinterpret_cast<float*>(dst + j * 4);
        atomicAdd(p + 0, x[j].x); atomicAdd(p + 1, x[j].y);
        atomicAdd(p + 2, x[j].z); atomicAdd(p + 3, x[j].w);
#endif
    }
}

// ---------------------------------------------------------------------------
// Fused dense layer, register-tiled, all-float4 smem traffic:
//   Block = 256 threads (16x16), tile = 64 rows x 64 cols, thread = 4x4.
//   sum = leaky(side@Wg+bg); bi = leaky((ego*side)@Wb+bb); ego = sum+bi
//   out[:, koff:+64] = l2norm(ego); side cleared during staging.
// smem: Wg 16KB + Wb 16KB + S 16KB + ES 16KB = 64KB, 2 barriers.
// ---------------------------------------------------------------------------
__global__ __launch_bounds__(256) void layer_kernel(
    const float* __restrict__ Wg, const float* __restrict__ bg,
    const float* __restrict__ Wb, const float* __restrict__ bb,
    float* __restrict__ out, int koff) {
    __shared__ float sWg[64 * 64];
    __shared__ float sWb[64 * 64];
    __shared__ float sS [64 * 64];
    __shared__ float sES[64 * 64];

    int tid = threadIdx.x;
    // stage weights (1024 float4 each, 4 per thread)
#pragma unroll
    for (int i = 0; i < 4; i++) {
        reinterpret_cast<float4*>(sWg)[tid + i * 256] =
            reinterpret_cast<const float4*>(Wg)[tid + i * 256];
        reinterpret_cast<float4*>(sWb)[tid + i * 256] =
            reinterpret_cast<const float4*>(Wb)[tid + i * 256];
    }

    int rowbase = blockIdx.x * 64;
    // stage A tiles: 64 rows x 16 float4; also clear side (vectorized)
#pragma unroll
    for (int p = 0; p < 4; p++) {
        int id = tid + p * 256;        // 0..1023 float4 slots
        int lr = id >> 4, lc = id & 15;
        int grow = rowbase + lr;
        float4 sv = make_float4(0.f, 0.f, 0.f, 0.f);
        float4 ev = sv;
        if (grow < NN) {
            int gi4 = grow * 16 + lc;
            sv = reinterpret_cast<float4*>(g_side)[gi4];
            ev = reinterpret_cast<float4*>(g_ego)[gi4];
            reinterpret_cast<float4*>(g_side)[gi4] = make_float4(0.f, 0.f, 0.f, 0.f);
        }
        reinterpret_cast<float4*>(sS )[id] = sv;
        reinterpret_cast<float4*>(sES)[id] =
            make_float4(ev.x * sv.x, ev.y * sv.y, ev.z * sv.z, ev.w * sv.w);
    }
    __syncthreads();

    int tx = tid & 15, ty = tid >> 4;
    int c0 = tx * 4,  r0 = ty * 4;

    float accg[4][4], accb[4][4];
#pragma unroll
    for (int j = 0; j < 4; j++)
#pragma unroll
        for (int i = 0; i < 4; i++) { accg[j][i] = 0.f; accb[j][i] = 0.f; }

#pragma unroll
    for (int k4 = 0; k4 < 16; k4++) {
        float4 a[4], a2[4];
#pragma unroll
        for (int j = 0; j < 4; j++) {
            a [j] = *reinterpret_cast<const float4*>(&sS [(r0 + j) * 64 + k4 * 4]);
            a2[j] = *reinterpret_cast<const float4*>(&sES[(r0 + j) * 64 + k4 * 4]);
        }
#pragma unroll
        for (int kk = 0; kk < 4; kk++) {
            float4 wg = *reinterpret_cast<const float4*>(&sWg[(k4 * 4 + kk) * 64 + c0]);
            float4 wb = *reinterpret_cast<const float4*>(&sWb[(k4 * 4 + kk) * 64 + c0]);
#pragma unroll
            for (int j = 0; j < 4; j++) {
                float av  = (kk == 0) ? a [j].x : (kk == 1) ? a [j].y : (kk == 2) ? a [j].z : a [j].w;
                float a2v = (kk == 0) ? a2[j].x : (kk == 1) ? a2[j].y : (kk == 2) ? a2[j].z : a2[j].w;
                accg[j][0] = fmaf(av, wg.x, accg[j][0]);
                accg[j][1] = fmaf(av, wg.y, accg[j][1]);
                accg[j][2] = fmaf(av, wg.z, accg[j][2]);
                accg[j][3] = fmaf(av, wg.w, accg[j][3]);
                accb[j][0] = fmaf(a2v, wb.x, accb[j][0]);
                accb[j][1] = fmaf(a2v, wb.y, accb[j][1]);
                accb[j][2] = fmaf(a2v, wb.z, accb[j][2]);
                accb[j][3] = fmaf(a2v, wb.w, accb[j][3]);
            }
        }
    }

    float4 bgv = __ldg(reinterpret_cast<const float4*>(bg + c0));
    float4 bbv = __ldg(reinterpret_cast<const float4*>(bb + c0));
    float bga[4] = {bgv.x, bgv.y, bgv.z, bgv.w};
    float bba[4] = {bbv.x, bbv.y, bbv.z, bbv.w};

#pragma unroll
    for (int j = 0; j < 4; j++) {
        float ne[4];
        float s = 0.f;
#pragma unroll
        for (int i = 0; i < 4; i++) {
            float g = accg[j][i] + bga[i];
            float b = accb[j][i] + bba[i];
            g = (g > 0.f) ? g : 0.2f * g;
            b = (b > 0.f) ? b : 0.2f * b;
            ne[i] = g + b;
            s = fmaf(ne[i], ne[i], s);
        }
        // reduce sum of squares across the 16 tx lanes (same row)
#pragma unroll
        for (int m = 8; m > 0; m >>= 1)
            s += __shfl_xor_sync(0xffffffffu, s, m);
        int grow = rowbase + r0 + j;
        if (grow < NN) {
            float inv = 1.f / fmaxf(sqrtf(s), 1e-12f);
            *reinterpret_cast<float4*>(&g_ego[grow * 64 + c0]) =
                make_float4(ne[0], ne[1], ne[2], ne[3]);
            *reinterpret_cast<float4*>(&out[grow * 256 + koff + c0]) =
                make_float4(ne[0] * inv, ne[1] * inv, ne[2] * inv, ne[3] * inv);
        }
    }
}

// ---------------------------------------------------------------------------
extern "C" void kernel_launch(void* const* d_in, const int* in_sizes, int n_in,
                              void* d_out, int out_size) {
    const float* ue = (const float*)d_in[0];
    const float* ie = (const float*)d_in[1];
    const float* Wg[3] = {(const float*)d_in[2],  (const float*)d_in[6],  (const float*)d_in[10]};
    const float* bg[3] = {(const float*)d_in[3],  (const float*)d_in[7],  (const float*)d_in[11]};
    const float* Wb[3] = {(const float*)d_in[4],  (const float*)d_in[8],  (const float*)d_in[12]};
    const float* bb[3] = {(const float*)d_in[5],  (const float*)d_in[9],  (const float*)d_in[13]};
    const float* vals = (const float*)d_in[14];
    const int*   rows = (const int*)d_in[15];
    const int*   cols = (const int*)d_in[16];
    float* out = (float*)d_out;

    prof_shim_kernel<<<1, 1>>>();   // shifts ncu -s 5 onto a layer_kernel launch
    init_kernel<<<(NN * 16 + 255) / 256, 256>>>(ue, ie, out);
    for (int k = 0; k < 3; k++) {
        spmm_kernel<<<(EE * 4 + 255) / 256, 256>>>(vals, rows, cols);
        layer_kernel<<<(NN + 63) / 64, 256>>>(Wg[k], bg[k], Wb[k], bb[k], out, (k + 1) * 64);
    }
}